// round 10
// baseline (speedup 1.0000x reference)
#include <cuda_runtime.h>
#include <cuda_bf16.h>
#include <cuda_fp16.h>
#include <cstdint>

// BiATT algebraic collapse: softmax over axis=1 of a [N,1] tensor == 1.0, so
// all four bi-attention branches are identity. cf = atoms @ (sum Wcc blocks) + bcc,
// pf = amino @ (sum Wcp blocks) + bcp  =>  two [6144x512]@[512x512] GEMMs.
// Single fp16 GEMM (fp32 accum), rel_err 2.93e-4 (stable since R7).
// R10: persistent 296-CTA scheduling (148 SMs x occ 2) to kill the 384-on-296
// wave quantization; tile mainloop unchanged from R9.

#define DIM     512
#define M_ROWS  6144
#define BM      128
#define BN      128
#define BK      64
#define NCHUNK  (DIM / BK)     // 8
#define NSTAGE  3
#define NTILES  384            // 4 nblk x 48 mblk x 2 z
#define NPERS   296            // persistent CTAs = 148 SMs x occ 2

// preformed fp16 operands
__device__ __half g_W[2][DIM * DIM];      // folded, transposed [N][K]
__device__ __half g_A[2][M_ROWS * DIM];   // fp16 copy of activations

// ---- smem: rows of 64 fp16 (128 B) padded to 144 B; conflict-free ldmatrix
#define PITCH    144
#define TILEB    (BM * PITCH)            // 18432 per tile
#define STAGE    (2 * TILEB)             // A + B = 36864 per stage
#define SM_A     0
#define SM_B     TILEB
#define SM_BIAS  (NSTAGE * STAGE)        // 110592
#define SM_TOT   (SM_BIAS + 512)         // 111104 dynamic (occ 2)

// ---------------------------------------------------------------- helpers
__device__ __forceinline__ uint32_t smem_u32(const void* p) {
    return (uint32_t)__cvta_generic_to_shared(p);
}
__device__ __forceinline__ void cp16(uint32_t dst, const void* src) {
    asm volatile("cp.async.cg.shared.global [%0], [%1], 16;"
                 :: "r"(dst), "l"(src));
}
__device__ __forceinline__ void cp_commit() {
    asm volatile("cp.async.commit_group;");
}
__device__ __forceinline__ void cp_wait1() {
    asm volatile("cp.async.wait_group 1;");
}
__device__ __forceinline__ void ldsm_x4(uint32_t* r, uint32_t addr) {
    asm volatile("ldmatrix.sync.aligned.m8n8.x4.shared.b16 {%0,%1,%2,%3}, [%4];"
                 : "=r"(r[0]), "=r"(r[1]), "=r"(r[2]), "=r"(r[3]) : "r"(addr));
}
__device__ __forceinline__ void mma_f16(float* d, const uint32_t* a,
                                        uint32_t b0, uint32_t b1) {
    asm volatile(
        "mma.sync.aligned.m16n8k16.row.col.f32.f16.f16.f32 "
        "{%0,%1,%2,%3}, {%4,%5,%6,%7}, {%8,%9}, {%0,%1,%2,%3};"
        : "+f"(d[0]), "+f"(d[1]), "+f"(d[2]), "+f"(d[3])
        : "r"(a[0]), "r"(a[1]), "r"(a[2]), "r"(a[3]), "r"(b0), "r"(b1));
}

// ---------------------------- fused prologue: fold-W (transpose) + convert-A
__global__ void __launch_bounds__(256)
prep_kernel(const float* __restrict__ atoms, const float* __restrict__ amino,
            const float* __restrict__ Wcc,   const float* __restrict__ Wcp) {
    const int z   = blockIdx.y;
    const int tid = threadIdx.x;

    if (blockIdx.x < 256) {
        // ---- fold: 32n x 32k tile per block (16 x 16 blocks per z)
        __shared__ float s[32][33];
        const float* __restrict__ W = z ? Wcp : Wcc;
        const int nb = blockIdx.x & 15;
        const int kb = blockIdx.x >> 4;
        const int n0 = nb * 32;
        const int k0 = kb * 32;
        const int tx = tid & 31;
        const int ty = tid >> 5;
        float v[4] = {0.f, 0.f, 0.f, 0.f};
#pragma unroll
        for (int b = 0; b < 4; b++) {
#pragma unroll
            for (int i = 0; i < 4; i++) {
                const int k = k0 + ty + i * 8;
                v[i] += W[(size_t)(b * DIM + k) * DIM + n0 + tx];
            }
        }
#pragma unroll
        for (int i = 0; i < 4; i++) s[tx][ty + i * 8] = v[i];
        __syncthreads();
#pragma unroll
        for (int i = 0; i < 4; i++) {
            const int n2 = n0 + ty + i * 8;
            const int k2 = k0 + tx;
            g_W[z][(size_t)n2 * DIM + k2] = __float2half_rn(s[ty + i * 8][tx]);
        }
    } else {
        // ---- convert: 2048 float4s per block (384 blocks per z), MLP=8
        const float* __restrict__ X = z ? amino : atoms;
        const size_t base = ((size_t)(blockIdx.x - 256) * 2048 + tid) * 4;
        float4 v[8];
#pragma unroll
        for (int i = 0; i < 8; i++)
            v[i] = *reinterpret_cast<const float4*>(&X[base + (size_t)i * 1024]);
#pragma unroll
        for (int i = 0; i < 8; i++) {
            __half2 h0 = __floats2half2_rn(v[i].x, v[i].y);
            __half2 h1 = __floats2half2_rn(v[i].z, v[i].w);
            uint2 o = make_uint2(*reinterpret_cast<uint32_t*>(&h0),
                                 *reinterpret_cast<uint32_t*>(&h1));
            *reinterpret_cast<uint2*>(&g_A[z][base + (size_t)i * 1024]) = o;
        }
    }
}

// --------------------------------------------------- persistent HMMA GEMM
// grid 296 x 1, 256 threads; warp tile 64x32; 3-stage cp.async per tile
__global__ void __launch_bounds__(256, 2)
biatt_gemm_kernel(const float* __restrict__ bcc,
                  const float* __restrict__ bcp,
                  float* __restrict__ out) {
    extern __shared__ __align__(16) char sm[];
    const uint32_t sbase = smem_u32(sm);

    const int tid  = threadIdx.x;
    const int wid  = tid >> 5;
    const int lane = tid & 31;
    const int mw   = (wid >> 2) * 64;
    const int nw   = (wid & 3) * 32;

    // per-thread copy slots: tile = 128 rows x 8 x 16B segs; 4 contiguous segs
    const int rowT = tid >> 1;
    const int segT = (tid & 1) * 4;
    const uint32_t dOffA = (uint32_t)(rowT * PITCH + segT * 16);
    const size_t   sOffA = (size_t)rowT * DIM + segT * 8;

    // ldmatrix lane address offsets
    const uint32_t aRowOff =
        (uint32_t)((mw + (lane & 15)) * PITCH + ((lane >> 4) << 4));
    const uint32_t bRowOff =
        (uint32_t)((nw + ((lane >> 4) << 3) + (lane & 7)) * PITCH +
                   (((lane >> 3) & 1) << 4));

    for (int t = blockIdx.x; t < NTILES; t += NPERS) {
        const int z   = t / 192;
        const int rem = t - z * 192;
        const int n0  = (rem & 3) * BN;
        const int m0  = (rem >> 2) * BM;

        const float* __restrict__ bias = z ? bcp : bcc;
        const __half* __restrict__ pA = g_A[z] + (size_t)m0 * DIM;
        const __half* __restrict__ pB = g_W[z] + (size_t)n0 * DIM;

        if (tid < 32) {   // stage bias slice [n0, n0+128)
            float4 bv = *reinterpret_cast<const float4*>(&bias[n0 + tid * 4]);
            *reinterpret_cast<float4*>(sm + SM_BIAS + tid * 16) = bv;
        }

        float acc[4][4][4];
#pragma unroll
        for (int i = 0; i < 4; i++)
#pragma unroll
            for (int j = 0; j < 4; j++)
#pragma unroll
                for (int e = 0; e < 4; e++) acc[i][j][e] = 0.f;

        // ---- preload chunks 0 and 1 into stages 0 and 1
#pragma unroll
        for (int p = 0; p < 2; ++p) {
            const uint32_t st = sbase + (uint32_t)(p * STAGE);
            const size_t ks = (size_t)p * BK;
#pragma unroll
            for (int s = 0; s < 4; ++s) {
                cp16(st + SM_A + dOffA + s * 16, pA + ks + sOffA + s * 8);
                cp16(st + SM_B + dOffA + s * 16, pB + ks + sOffA + s * 8);
            }
            cp_commit();
        }

        int stage = 0;
        for (int c = 0; c < NCHUNK; ++c) {
            cp_wait1();
            __syncthreads();

            // ---- issue chunk c+2 copies into the freed stage
            if (c + 2 < NCHUNK) {
                const int ns = (stage + 2 >= NSTAGE) ? stage + 2 - NSTAGE : stage + 2;
                const uint32_t nxt = sbase + (uint32_t)(ns * STAGE);
                const size_t ks = (size_t)(c + 2) * BK;
#pragma unroll
                for (int s = 0; s < 4; ++s) {
                    cp16(nxt + SM_A + dOffA + s * 16, pA + ks + sOffA + s * 8);
                    cp16(nxt + SM_B + dOffA + s * 16, pB + ks + sOffA + s * 8);
                }
                cp_commit();
            } else {
                cp_commit();   // uniform group counts for wait_group 1
            }

            const uint32_t cur = sbase + (uint32_t)(stage * STAGE);
            const uint32_t aP = cur + SM_A + aRowOff;
            const uint32_t bP = cur + SM_B + bRowOff;
#pragma unroll
            for (int ks = 0; ks < 4; ++ks) {
                const uint32_t ko = ks * 32;
                uint32_t af[4][4];
#pragma unroll
                for (int mt = 0; mt < 4; ++mt)
                    ldsm_x4(af[mt], aP + mt * (16 * PITCH) + ko);
#pragma unroll
                for (int j2 = 0; j2 < 2; ++j2) {
                    uint32_t bf[4];
                    ldsm_x4(bf, bP + j2 * (16 * PITCH) + ko);
#pragma unroll
                    for (int mt = 0; mt < 4; ++mt) {
                        mma_f16(acc[mt][j2 * 2],     af[mt], bf[0], bf[1]);
                        mma_f16(acc[mt][j2 * 2 + 1], af[mt], bf[2], bf[3]);
                    }
                }
            }
            stage = (stage + 1 >= NSTAGE) ? 0 : stage + 1;
        }

        // ---- epilogue: +bias, float2 stores
        float* C = out + (size_t)z * M_ROWS * DIM;
        const float* sb = reinterpret_cast<const float*>(sm + SM_BIAS);
#pragma unroll
        for (int mt = 0; mt < 4; ++mt) {
            const int r0 = m0 + mw + mt * 16 + (lane >> 2);
#pragma unroll
            for (int nt = 0; nt < 4; ++nt) {
                const int cl = nw + nt * 8 + (lane & 3) * 2;
                const float b0 = sb[cl], b1 = sb[cl + 1];
                float2 v0 = make_float2(acc[mt][nt][0] + b0, acc[mt][nt][1] + b1);
                float2 v1 = make_float2(acc[mt][nt][2] + b0, acc[mt][nt][3] + b1);
                *reinterpret_cast<float2*>(&C[(size_t)r0 * DIM + n0 + cl]) = v0;
                *reinterpret_cast<float2*>(&C[(size_t)(r0 + 8) * DIM + n0 + cl]) = v1;
            }
        }
        __syncthreads();   // protect SM_BIAS before next tile overwrites it
    }
}

// ------------------------------------------------------------------ launch
extern "C" void kernel_launch(void* const* d_in, const int* in_sizes, int n_in,
                              void* d_out, int out_size) {
    const float* atoms = (const float*)d_in[0];
    const float* amino = (const float*)d_in[1];
    const float* Wcc   = (const float*)d_in[15];
    const float* bcc   = (const float*)d_in[16];
    const float* Wcp   = (const float*)d_in[17];
    const float* bcp   = (const float*)d_in[18];
    float* out = (float*)d_out;

    static bool attr_set = false;
    if (!attr_set) {
        cudaFuncSetAttribute(biatt_gemm_kernel,
                             cudaFuncAttributeMaxDynamicSharedMemorySize, SM_TOT);
        attr_set = true;
    }

    prep_kernel<<<dim3(256 + 384, 2), 256>>>(atoms, amino, Wcc, Wcp);
    biatt_gemm_kernel<<<NPERS, 256, SM_TOT>>>(bcc, bcp, out);
}

// round 11
// speedup vs baseline: 1.2194x; 1.2194x over previous
#include <cuda_runtime.h>
#include <cuda_bf16.h>
#include <cuda_fp16.h>
#include <cstdint>

// BiATT algebraic collapse: softmax over axis=1 of a [N,1] tensor == 1.0, so
// all four bi-attention branches are identity. cf = atoms @ (sum Wcc blocks) + bcc,
// pf = amino @ (sum Wcp blocks) + bcp  =>  two [6144x512]@[512x512] GEMMs.
// Single fp16 GEMM (fp32 accum), rel_err 2.93e-4 (stable since R7).
// R11: GEMM was LDGSTS-ISSUE-bound (2048 cp.async x rt8 per chunk ~ 4x MMA cost).
// Replace with cp.async.bulk: prep writes operands in tile-blocked, pre-swizzled
// 16KB blocks; one bulk copy per tile per chunk, mbarrier completion.

#define DIM     512
#define M_ROWS  6144
#define BM      128
#define BN      128
#define BK      64
#define NCHUNK  (DIM / BK)     // 8
#define NTILES  384            // 4 nblk x 48 mblk x 2 z
#define NPERS   296            // persistent CTAs = 148 SMs x occ 2
#define BLKB    16384          // 16KB block: 128 rows x 64 fp16, swizzled

// tile-blocked, pre-swizzled fp16 operands (uint4 => 16B-aligned for bulk copy)
__device__ uint4 g_A4[2 * 48 * 8 * (BLKB / 16)];   // [z][mtile][chunk][16KB]
__device__ uint4 g_W4[2 * 4 * 8 * (BLKB / 16)];    // [z][ntile][chunk][16KB]

// ---- smem: 3 stages x (A 16KB + B 16KB); mbarriers; bias
#define SM_A      0
#define SM_B      16384
#define SM_STAGE  32768
#define SM_MBAR   (3 * SM_STAGE)        // 98304
#define SM_BIAS   (SM_MBAR + 64)        // 98368
#define SM_TOT    (SM_BIAS + 512)       // 98880 dynamic (occ 2)

// ---------------------------------------------------------------- helpers
__device__ __forceinline__ uint32_t smem_u32(const void* p) {
    return (uint32_t)__cvta_generic_to_shared(p);
}
__device__ __forceinline__ uint32_t sw128(uint32_t off) {
    return off ^ ((off >> 3) & 0x70);
}
__device__ __forceinline__ void bulk_cp(uint32_t dst, const void* src,
                                        uint32_t bytes, uint32_t mbar) {
    asm volatile(
        "cp.async.bulk.shared::cluster.global.mbarrier::complete_tx::bytes "
        "[%0], [%1], %2, [%3];"
        :: "r"(dst), "l"(src), "r"(bytes), "r"(mbar) : "memory");
}
__device__ __forceinline__ void mbar_init(uint32_t mbar, uint32_t cnt) {
    asm volatile("mbarrier.init.shared.b64 [%0], %1;" :: "r"(mbar), "r"(cnt)
                 : "memory");
}
__device__ __forceinline__ void mbar_expect(uint32_t mbar, uint32_t tx) {
    asm volatile("mbarrier.arrive.expect_tx.shared.b64 _, [%0], %1;"
                 :: "r"(mbar), "r"(tx) : "memory");
}
__device__ __forceinline__ void mbar_wait(uint32_t mbar, uint32_t parity) {
    asm volatile(
        "{\n\t.reg .pred P1;\n\t"
        "WAIT_LOOP_%=:\n\t"
        "mbarrier.try_wait.parity.acquire.cta.shared::cta.b64 P1, [%0], %1, 0x989680;\n\t"
        "@P1 bra.uni WAIT_DONE_%=;\n\t"
        "bra.uni WAIT_LOOP_%=;\n\t"
        "WAIT_DONE_%=:\n\t}"
        :: "r"(mbar), "r"(parity) : "memory");
}
__device__ __forceinline__ void ldsm_x4(uint32_t* r, uint32_t addr) {
    asm volatile("ldmatrix.sync.aligned.m8n8.x4.shared.b16 {%0,%1,%2,%3}, [%4];"
                 : "=r"(r[0]), "=r"(r[1]), "=r"(r[2]), "=r"(r[3]) : "r"(addr));
}
__device__ __forceinline__ void mma_f16(float* d, const uint32_t* a,
                                        uint32_t b0, uint32_t b1) {
    asm volatile(
        "mma.sync.aligned.m16n8k16.row.col.f32.f16.f16.f32 "
        "{%0,%1,%2,%3}, {%4,%5,%6,%7}, {%8,%9}, {%0,%1,%2,%3};"
        : "+f"(d[0]), "+f"(d[1]), "+f"(d[2]), "+f"(d[3])
        : "r"(a[0]), "r"(a[1]), "r"(a[2]), "r"(a[3]), "r"(b0), "r"(b1));
}

// ---------------------------- fused prologue: fold-W + convert-A, blocked+swizzled
// grid (256 + 384, 2):  x<256 fold-W,  x>=256 convert-A
__global__ void __launch_bounds__(256)
prep_kernel(const float* __restrict__ atoms, const float* __restrict__ amino,
            const float* __restrict__ Wcc,   const float* __restrict__ Wcp) {
    const int z   = blockIdx.y;
    const int tid = threadIdx.x;
    char* gA = reinterpret_cast<char*>(g_A4);
    char* gW = reinterpret_cast<char*>(g_W4);

    if (blockIdx.x < 256) {
        // ---- fold: 32n x 32k transpose tile; write into blocked swizzled g_W
        __shared__ float s[32][33];
        const float* __restrict__ W = z ? Wcp : Wcc;
        const int nb = blockIdx.x & 15;
        const int kb = blockIdx.x >> 4;
        const int n0 = nb * 32;
        const int k0 = kb * 32;
        const int tx = tid & 31;
        const int ty = tid >> 5;
        float v[4] = {0.f, 0.f, 0.f, 0.f};
#pragma unroll
        for (int b = 0; b < 4; b++) {
#pragma unroll
            for (int i = 0; i < 4; i++) {
                const int k = k0 + ty + i * 8;
                v[i] += W[(size_t)(b * DIM + k) * DIM + n0 + tx];
            }
        }
#pragma unroll
        for (int i = 0; i < 4; i++) s[tx][ty + i * 8] = v[i];
        __syncthreads();
#pragma unroll
        for (int i = 0; i < 4; i++) {
            const int n2 = n0 + ty + i * 8;
            const int k2 = k0 + tx;
            const int ntile = n2 >> 7;
            const int c     = k2 >> 6;
            const size_t base = (size_t)(((z * 4 + ntile) * 8 + c)) * BLKB;
            const uint32_t off = sw128((uint32_t)((n2 & 127) * 128 + (k2 & 63) * 2));
            *reinterpret_cast<__half*>(gW + base + off) =
                __float2half_rn(s[ty + i * 8][tx]);
        }
    } else {
        // ---- convert: one 16KB block per CUDA block (48 mtiles x 8 chunks)
        const float* __restrict__ X = z ? amino : atoms;
        const int cb = blockIdx.x - 256;        // 0..383
        const int m  = cb >> 3;
        const int c  = cb & 7;
        const int r  = tid >> 1;                // row 0..127
        const int h  = tid & 1;                 // col half (32 floats)
        const float* src = &X[(size_t)(m * 128 + r) * DIM + c * 64 + h * 32];
        float4 v[8];
#pragma unroll
        for (int q = 0; q < 8; q++)
            v[q] = *reinterpret_cast<const float4*>(src + q * 4);
        char* dst = gA + (size_t)((z * 48 + m) * 8 + c) * BLKB;
#pragma unroll
        for (int j = 0; j < 4; j++) {           // 4 x 16B stores (8 fp16 each)
            __half2 h0 = __floats2half2_rn(v[2 * j].x,     v[2 * j].y);
            __half2 h1 = __floats2half2_rn(v[2 * j].z,     v[2 * j].w);
            __half2 h2 = __floats2half2_rn(v[2 * j + 1].x, v[2 * j + 1].y);
            __half2 h3 = __floats2half2_rn(v[2 * j + 1].z, v[2 * j + 1].w);
            uint4 o = make_uint4(*reinterpret_cast<uint32_t*>(&h0),
                                 *reinterpret_cast<uint32_t*>(&h1),
                                 *reinterpret_cast<uint32_t*>(&h2),
                                 *reinterpret_cast<uint32_t*>(&h3));
            const uint32_t off = sw128((uint32_t)(r * 128 + h * 64 + j * 16));
            *reinterpret_cast<uint4*>(dst + off) = o;
        }
    }
}

// --------------------------------------------------- persistent HMMA GEMM
// grid 296, 256 threads; warp tile 64x32; 3-stage bulk-copy pipeline
__global__ void __launch_bounds__(256, 2)
biatt_gemm_kernel(const float* __restrict__ bcc,
                  const float* __restrict__ bcp,
                  float* __restrict__ out) {
    extern __shared__ __align__(16) char sm[];
    const uint32_t sbase = smem_u32(sm);

    const int tid  = threadIdx.x;
    const int wid  = tid >> 5;
    const int lane = tid & 31;
    const int mw   = (wid >> 2) * 64;
    const int nw   = (wid & 3) * 32;
    const char* gA = reinterpret_cast<const char*>(g_A4);
    const char* gW = reinterpret_cast<const char*>(g_W4);

    // ldmatrix lane constants (swizzled layout: rows of 128B, XOR mask (R&7)<<4)
    const int      Ra    = mw + (lane & 15);
    const uint32_t rowA  = (uint32_t)Ra * 128;
    const uint32_t xA    = (uint32_t)((Ra & 7) << 4);
    const uint32_t colA0 = (uint32_t)((lane >> 4) << 4);
    const int      Rb    = nw + ((lane >> 4) << 3) + (lane & 7);
    const uint32_t rowB  = (uint32_t)Rb * 128;
    const uint32_t xB    = (uint32_t)((Rb & 7) << 4);
    const uint32_t colB0 = (uint32_t)(((lane >> 3) & 1) << 4);

    // mbarrier init
    if (tid == 0) {
#pragma unroll
        for (int s = 0; s < 3; ++s) mbar_init(sbase + SM_MBAR + s * 8, 1);
    }
    __syncthreads();

    int cur = 0;
    uint32_t phm = 0;      // per-stage parity bits

    for (int t = blockIdx.x; t < NTILES; t += NPERS) {
        const int z     = t / 192;
        const int rem   = t - z * 192;
        const int ntile = rem & 3;
        const int mtile = rem >> 2;
        const int n0    = ntile * BN;
        const int m0    = mtile * BM;
        const char* srcA = gA + (size_t)((z * 48 + mtile) * 8) * BLKB;
        const char* srcB = gW + (size_t)((z * 4 + ntile) * 8) * BLKB;
        const float* __restrict__ bias = z ? bcp : bcc;

        if (tid < 32) {
            float4 bv = *reinterpret_cast<const float4*>(&bias[n0 + tid * 4]);
            *reinterpret_cast<float4*>(sm + SM_BIAS + tid * 16) = bv;
        }

        float acc[4][4][4];
#pragma unroll
        for (int i = 0; i < 4; i++)
#pragma unroll
            for (int j = 0; j < 4; j++)
#pragma unroll
                for (int e = 0; e < 4; e++) acc[i][j][e] = 0.f;

        // ---- preload chunks 0,1 (stages free: end-of-tile / init syncthreads)
        if (tid == 0) {
#pragma unroll
            for (int p = 0; p < 2; ++p) {
                const int s = (cur + p) % 3;
                const uint32_t mb = sbase + SM_MBAR + s * 8;
                const uint32_t st = sbase + (uint32_t)(s * SM_STAGE);
                mbar_expect(mb, 2 * BLKB);
                bulk_cp(st + SM_A, srcA + (size_t)p * BLKB, BLKB, mb);
                bulk_cp(st + SM_B, srcB + (size_t)p * BLKB, BLKB, mb);
            }
        }

        for (int c = 0; c < NCHUNK; ++c) {
            if (c > 0) __syncthreads();   // chunk c-1 reads retired everywhere

            // refill stage (cur+2)%3 with chunk c+2
            if (c + 2 < NCHUNK && tid == 0) {
                const int s2 = (cur + 2 >= 3) ? cur - 1 : cur + 2;
                const uint32_t mb = sbase + SM_MBAR + s2 * 8;
                const uint32_t st = sbase + (uint32_t)(s2 * SM_STAGE);
                mbar_expect(mb, 2 * BLKB);
                bulk_cp(st + SM_A, srcA + (size_t)(c + 2) * BLKB, BLKB, mb);
                bulk_cp(st + SM_B, srcB + (size_t)(c + 2) * BLKB, BLKB, mb);
            }

            // wait chunk c data
            mbar_wait(sbase + SM_MBAR + cur * 8, (phm >> cur) & 1u);
            phm ^= 1u << cur;

            const uint32_t stb = sbase + (uint32_t)(cur * SM_STAGE);
            const uint32_t aBase = stb + SM_A + rowA;
            const uint32_t bBase = stb + SM_B + rowB;
#pragma unroll
            for (int ks = 0; ks < 4; ++ks) {
                const uint32_t cb = (uint32_t)(ks * 32);
                const uint32_t aCol = (colA0 + cb) ^ xA;
                const uint32_t bCol = (colB0 + cb) ^ xB;
                uint32_t af[4][4];
#pragma unroll
                for (int mt = 0; mt < 4; ++mt)
                    ldsm_x4(af[mt], aBase + mt * 2048 + aCol);
#pragma unroll
                for (int j2 = 0; j2 < 2; ++j2) {
                    uint32_t bf[4];
                    ldsm_x4(bf, bBase + j2 * 2048 + bCol);
#pragma unroll
                    for (int mt = 0; mt < 4; ++mt) {
                        mma_f16(acc[mt][j2 * 2],     af[mt], bf[0], bf[1]);
                        mma_f16(acc[mt][j2 * 2 + 1], af[mt], bf[2], bf[3]);
                    }
                }
            }
            cur = (cur + 1 >= 3) ? 0 : cur + 1;
        }

        // ---- epilogue: +bias, float2 stores
        float* C = out + (size_t)z * M_ROWS * DIM;
        const float* sb = reinterpret_cast<const float*>(sm + SM_BIAS);
#pragma unroll
        for (int mt = 0; mt < 4; ++mt) {
            const int r0 = m0 + mw + mt * 16 + (lane >> 2);
#pragma unroll
            for (int nt = 0; nt < 4; ++nt) {
                const int cl = nw + nt * 8 + (lane & 3) * 2;
                const float b0 = sb[cl], b1 = sb[cl + 1];
                float2 v0 = make_float2(acc[mt][nt][0] + b0, acc[mt][nt][1] + b1);
                float2 v1 = make_float2(acc[mt][nt][2] + b0, acc[mt][nt][3] + b1);
                *reinterpret_cast<float2*>(&C[(size_t)r0 * DIM + n0 + cl]) = v0;
                *reinterpret_cast<float2*>(&C[(size_t)(r0 + 8) * DIM + n0 + cl]) = v1;
            }
        }
        __syncthreads();   // stages + bias free for next tile
    }
}

// ------------------------------------------------------------------ launch
extern "C" void kernel_launch(void* const* d_in, const int* in_sizes, int n_in,
                              void* d_out, int out_size) {
    const float* atoms = (const float*)d_in[0];
    const float* amino = (const float*)d_in[1];
    const float* Wcc   = (const float*)d_in[15];
    const float* bcc   = (const float*)d_in[16];
    const float* Wcp   = (const float*)d_in[17];
    const float* bcp   = (const float*)d_in[18];
    float* out = (float*)d_out;

    static bool attr_set = false;
    if (!attr_set) {
        cudaFuncSetAttribute(biatt_gemm_kernel,
                             cudaFuncAttributeMaxDynamicSharedMemorySize, SM_TOT);
        attr_set = true;
    }

    prep_kernel<<<dim3(256 + 384, 2), 256>>>(atoms, amino, Wcc, Wcp);
    biatt_gemm_kernel<<<NPERS, 256, SM_TOT>>>(bcc, bcp, out);
}

// round 12
// speedup vs baseline: 1.4588x; 1.1963x over previous
#include <cuda_runtime.h>
#include <cuda_bf16.h>
#include <cuda_fp16.h>
#include <cstdint>

// BiATT algebraic collapse: softmax over axis=1 of a [N,1] tensor == 1.0, so
// all four bi-attention branches are identity. cf = atoms @ (sum Wcc blocks) + bcc,
// pf = amino @ (sum Wcp blocks) + bcp  =>  two [6144x512]@[512x512] GEMMs.
// Single fp16 GEMM (fp32 accum), rel_err 2.93e-4 (stable since R7).
// R12: (a) convert-A with lane-coalesced LDGs (R11 had nL=32 per LDG);
//      (b) GEMM 512 threads / 16 warps (warp tile 32x32) -> 8 warps/SMSP
//          to hide LDSM/mbarrier latency. Bulk-copy pipeline unchanged.

#define DIM     512
#define M_ROWS  6144
#define BM      128
#define BN      128
#define BK      64
#define NCHUNK  (DIM / BK)     // 8
#define NTILES  384            // 4 nblk x 48 mblk x 2 z
#define NPERS   296            // persistent CTAs = 148 SMs x occ 2
#define BLKB    16384          // 16KB block: 128 rows x 64 fp16, swizzled

// tile-blocked, pre-swizzled fp16 operands (uint4 => 16B-aligned for bulk copy)
__device__ uint4 g_A4[2 * 48 * 8 * (BLKB / 16)];   // [z][mtile][chunk][16KB]
__device__ uint4 g_W4[2 * 4 * 8 * (BLKB / 16)];    // [z][ntile][chunk][16KB]

// ---- smem: 3 stages x (A 16KB + B 16KB); mbarriers; bias
#define SM_A      0
#define SM_B      16384
#define SM_STAGE  32768
#define SM_MBAR   (3 * SM_STAGE)        // 98304
#define SM_BIAS   (SM_MBAR + 64)        // 98368
#define SM_TOT    (SM_BIAS + 512)       // 98880 dynamic (occ 2)

// ---------------------------------------------------------------- helpers
__device__ __forceinline__ uint32_t smem_u32(const void* p) {
    return (uint32_t)__cvta_generic_to_shared(p);
}
__device__ __forceinline__ uint32_t sw128(uint32_t off) {
    return off ^ ((off >> 3) & 0x70);
}
__device__ __forceinline__ void bulk_cp(uint32_t dst, const void* src,
                                        uint32_t bytes, uint32_t mbar) {
    asm volatile(
        "cp.async.bulk.shared::cluster.global.mbarrier::complete_tx::bytes "
        "[%0], [%1], %2, [%3];"
        :: "r"(dst), "l"(src), "r"(bytes), "r"(mbar) : "memory");
}
__device__ __forceinline__ void mbar_init(uint32_t mbar, uint32_t cnt) {
    asm volatile("mbarrier.init.shared.b64 [%0], %1;" :: "r"(mbar), "r"(cnt)
                 : "memory");
}
__device__ __forceinline__ void mbar_expect(uint32_t mbar, uint32_t tx) {
    asm volatile("mbarrier.arrive.expect_tx.shared.b64 _, [%0], %1;"
                 :: "r"(mbar), "r"(tx) : "memory");
}
__device__ __forceinline__ void mbar_wait(uint32_t mbar, uint32_t parity) {
    asm volatile(
        "{\n\t.reg .pred P1;\n\t"
        "WAIT_LOOP_%=:\n\t"
        "mbarrier.try_wait.parity.acquire.cta.shared::cta.b64 P1, [%0], %1, 0x989680;\n\t"
        "@P1 bra.uni WAIT_DONE_%=;\n\t"
        "bra.uni WAIT_LOOP_%=;\n\t"
        "WAIT_DONE_%=:\n\t}"
        :: "r"(mbar), "r"(parity) : "memory");
}
__device__ __forceinline__ void ldsm_x4(uint32_t* r, uint32_t addr) {
    asm volatile("ldmatrix.sync.aligned.m8n8.x4.shared.b16 {%0,%1,%2,%3}, [%4];"
                 : "=r"(r[0]), "=r"(r[1]), "=r"(r[2]), "=r"(r[3]) : "r"(addr));
}
__device__ __forceinline__ void mma_f16(float* d, const uint32_t* a,
                                        uint32_t b0, uint32_t b1) {
    asm volatile(
        "mma.sync.aligned.m16n8k16.row.col.f32.f16.f16.f32 "
        "{%0,%1,%2,%3}, {%4,%5,%6,%7}, {%8,%9}, {%0,%1,%2,%3};"
        : "+f"(d[0]), "+f"(d[1]), "+f"(d[2]), "+f"(d[3])
        : "r"(a[0]), "r"(a[1]), "r"(a[2]), "r"(a[3]), "r"(b0), "r"(b1));
}

// ---------------------------- fused prologue: fold-W + convert-A, blocked+swizzled
// grid (256 + 384, 2):  x<256 fold-W,  x>=256 convert-A
__global__ void __launch_bounds__(256)
prep_kernel(const float* __restrict__ atoms, const float* __restrict__ amino,
            const float* __restrict__ Wcc,   const float* __restrict__ Wcp) {
    const int z   = blockIdx.y;
    const int tid = threadIdx.x;
    char* gA = reinterpret_cast<char*>(g_A4);
    char* gW = reinterpret_cast<char*>(g_W4);

    if (blockIdx.x < 256) {
        // ---- fold: 32n x 32k transpose tile; write into blocked swizzled g_W
        __shared__ float s[32][33];
        const float* __restrict__ W = z ? Wcp : Wcc;
        const int nb = blockIdx.x & 15;
        const int kb = blockIdx.x >> 4;
        const int n0 = nb * 32;
        const int k0 = kb * 32;
        const int tx = tid & 31;
        const int ty = tid >> 5;
        float v[4] = {0.f, 0.f, 0.f, 0.f};
#pragma unroll
        for (int b = 0; b < 4; b++) {
#pragma unroll
            for (int i = 0; i < 4; i++) {
                const int k = k0 + ty + i * 8;
                v[i] += W[(size_t)(b * DIM + k) * DIM + n0 + tx];
            }
        }
#pragma unroll
        for (int i = 0; i < 4; i++) s[tx][ty + i * 8] = v[i];
        __syncthreads();
#pragma unroll
        for (int i = 0; i < 4; i++) {
            const int n2 = n0 + ty + i * 8;
            const int k2 = k0 + tx;
            const int ntile = n2 >> 7;
            const int c     = k2 >> 6;
            const size_t base = (size_t)(((z * 4 + ntile) * 8 + c)) * BLKB;
            const uint32_t off = sw128((uint32_t)((n2 & 127) * 128 + (k2 & 63) * 2));
            *reinterpret_cast<__half*>(gW + base + off) =
                __float2half_rn(s[ty + i * 8][tx]);
        }
    } else {
        // ---- convert: one 16KB block per CUDA block; LANE-COALESCED reads.
        // gidx = it*1024 + tid*4: 16 lanes cover 64 consecutive floats of one
        // row (256B, nL=4 per LDG.128); MLP=8 via upfront loads.
        const float* __restrict__ X = z ? amino : atoms;
        const int cb = blockIdx.x - 256;        // 0..383
        const int m  = cb >> 3;
        const int c  = cb & 7;
        float4 v[8];
        int   rows[8], cols[8];
#pragma unroll
        for (int it = 0; it < 8; it++) {
            const int gidx = it * 1024 + tid * 4;   // 0..8191
            rows[it] = gidx >> 6;                    // 0..127
            cols[it] = gidx & 63;                    // 0..63 (mult of 4)
            v[it] = *reinterpret_cast<const float4*>(
                &X[(size_t)(m * 128 + rows[it]) * DIM + c * 64 + cols[it]]);
        }
        char* dst = gA + (size_t)((z * 48 + m) * 8 + c) * BLKB;
#pragma unroll
        for (int it = 0; it < 8; it++) {
            __half2 h0 = __floats2half2_rn(v[it].x, v[it].y);
            __half2 h1 = __floats2half2_rn(v[it].z, v[it].w);
            uint2 o = make_uint2(*reinterpret_cast<uint32_t*>(&h0),
                                 *reinterpret_cast<uint32_t*>(&h1));
            const uint32_t off =
                sw128((uint32_t)(rows[it] * 128 + cols[it] * 2));
            *reinterpret_cast<uint2*>(dst + off) = o;   // 8B store, line-local
        }
    }
}

// --------------------------------------------------- persistent HMMA GEMM
// grid 296, 512 threads (16 warps, warp tile 32x32); 3-stage bulk pipeline
__global__ void __launch_bounds__(512, 2)
biatt_gemm_kernel(const float* __restrict__ bcc,
                  const float* __restrict__ bcp,
                  float* __restrict__ out) {
    extern __shared__ __align__(16) char sm[];
    const uint32_t sbase = smem_u32(sm);

    const int tid  = threadIdx.x;
    const int wid  = tid >> 5;
    const int lane = tid & 31;
    const int mw   = (wid >> 2) * 32;     // warp m offset (0,32,64,96)
    const int nw   = (wid & 3) * 32;      // warp n offset (0,32,64,96)
    const char* gA = reinterpret_cast<const char*>(g_A4);
    const char* gW = reinterpret_cast<const char*>(g_W4);

    // ldmatrix lane constants (swizzled layout: rows of 128B, XOR (R&7)<<4)
    const int      Ra    = mw + (lane & 15);
    const uint32_t rowA  = (uint32_t)Ra * 128;
    const uint32_t xA    = (uint32_t)((Ra & 7) << 4);
    const uint32_t colA0 = (uint32_t)((lane >> 4) << 4);
    const int      Rb    = nw + ((lane >> 4) << 3) + (lane & 7);
    const uint32_t rowB  = (uint32_t)Rb * 128;
    const uint32_t xB    = (uint32_t)((Rb & 7) << 4);
    const uint32_t colB0 = (uint32_t)(((lane >> 3) & 1) << 4);

    if (tid == 0) {
#pragma unroll
        for (int s = 0; s < 3; ++s) mbar_init(sbase + SM_MBAR + s * 8, 1);
    }
    __syncthreads();

    int cur = 0;
    uint32_t phm = 0;      // per-stage parity bits

    for (int t = blockIdx.x; t < NTILES; t += NPERS) {
        const int z     = t / 192;
        const int rem   = t - z * 192;
        const int ntile = rem & 3;
        const int mtile = rem >> 2;
        const int n0    = ntile * BN;
        const int m0    = mtile * BM;
        const char* srcA = gA + (size_t)((z * 48 + mtile) * 8) * BLKB;
        const char* srcB = gW + (size_t)((z * 4 + ntile) * 8) * BLKB;
        const float* __restrict__ bias = z ? bcp : bcc;

        if (tid < 32) {
            float4 bv = *reinterpret_cast<const float4*>(&bias[n0 + tid * 4]);
            *reinterpret_cast<float4*>(sm + SM_BIAS + tid * 16) = bv;
        }

        float acc[2][4][4];
#pragma unroll
        for (int i = 0; i < 2; i++)
#pragma unroll
            for (int j = 0; j < 4; j++)
#pragma unroll
                for (int e = 0; e < 4; e++) acc[i][j][e] = 0.f;

        // ---- preload chunks 0,1
        if (tid == 0) {
#pragma unroll
            for (int p = 0; p < 2; ++p) {
                const int s = (cur + p) % 3;
                const uint32_t mb = sbase + SM_MBAR + s * 8;
                const uint32_t st = sbase + (uint32_t)(s * SM_STAGE);
                mbar_expect(mb, 2 * BLKB);
                bulk_cp(st + SM_A, srcA + (size_t)p * BLKB, BLKB, mb);
                bulk_cp(st + SM_B, srcB + (size_t)p * BLKB, BLKB, mb);
            }
        }

        for (int c = 0; c < NCHUNK; ++c) {
            if (c > 0) __syncthreads();   // chunk c-1 reads retired everywhere

            // refill stage (cur+2)%3 with chunk c+2
            if (c + 2 < NCHUNK && tid == 0) {
                const int s2 = (cur + 2 >= 3) ? cur - 1 : cur + 2;
                const uint32_t mb = sbase + SM_MBAR + s2 * 8;
                const uint32_t st = sbase + (uint32_t)(s2 * SM_STAGE);
                mbar_expect(mb, 2 * BLKB);
                bulk_cp(st + SM_A, srcA + (size_t)(c + 2) * BLKB, BLKB, mb);
                bulk_cp(st + SM_B, srcB + (size_t)(c + 2) * BLKB, BLKB, mb);
            }

            // wait chunk c data
            mbar_wait(sbase + SM_MBAR + cur * 8, (phm >> cur) & 1u);
            phm ^= 1u << cur;

            const uint32_t stb = sbase + (uint32_t)(cur * SM_STAGE);
            const uint32_t aBase = stb + SM_A + rowA;
            const uint32_t bBase = stb + SM_B + rowB;
#pragma unroll
            for (int ks = 0; ks < 4; ++ks) {
                const uint32_t cb = (uint32_t)(ks * 32);
                const uint32_t aCol = (colA0 + cb) ^ xA;
                const uint32_t bCol = (colB0 + cb) ^ xB;
                uint32_t af[2][4];
#pragma unroll
                for (int mt = 0; mt < 2; ++mt)
                    ldsm_x4(af[mt], aBase + mt * 2048 + aCol);
#pragma unroll
                for (int j2 = 0; j2 < 2; ++j2) {
                    uint32_t bf[4];
                    ldsm_x4(bf, bBase + j2 * 2048 + bCol);
#pragma unroll
                    for (int mt = 0; mt < 2; ++mt) {
                        mma_f16(acc[mt][j2 * 2],     af[mt], bf[0], bf[1]);
                        mma_f16(acc[mt][j2 * 2 + 1], af[mt], bf[2], bf[3]);
                    }
                }
            }
            cur = (cur + 1 >= 3) ? 0 : cur + 1;
        }

        // ---- epilogue: +bias, float2 stores
        float* C = out + (size_t)z * M_ROWS * DIM;
        const float* sb = reinterpret_cast<const float*>(sm + SM_BIAS);
#pragma unroll
        for (int mt = 0; mt < 2; ++mt) {
            const int r0 = m0 + mw + mt * 16 + (lane >> 2);
#pragma unroll
            for (int nt = 0; nt < 4; ++nt) {
                const int cl = nw + nt * 8 + (lane & 3) * 2;
                const float b0 = sb[cl], b1 = sb[cl + 1];
                float2 v0 = make_float2(acc[mt][nt][0] + b0, acc[mt][nt][1] + b1);
                float2 v1 = make_float2(acc[mt][nt][2] + b0, acc[mt][nt][3] + b1);
                *reinterpret_cast<float2*>(&C[(size_t)r0 * DIM + n0 + cl]) = v0;
                *reinterpret_cast<float2*>(&C[(size_t)(r0 + 8) * DIM + n0 + cl]) = v1;
            }
        }
        __syncthreads();   // stages + bias free for next tile
    }
}

// ------------------------------------------------------------------ launch
extern "C" void kernel_launch(void* const* d_in, const int* in_sizes, int n_in,
                              void* d_out, int out_size) {
    const float* atoms = (const float*)d_in[0];
    const float* amino = (const float*)d_in[1];
    const float* Wcc   = (const float*)d_in[15];
    const float* bcc   = (const float*)d_in[16];
    const float* Wcp   = (const float*)d_in[17];
    const float* bcp   = (const float*)d_in[18];
    float* out = (float*)d_out;

    static bool attr_set = false;
    if (!attr_set) {
        cudaFuncSetAttribute(biatt_gemm_kernel,
                             cudaFuncAttributeMaxDynamicSharedMemorySize, SM_TOT);
        attr_set = true;
    }

    prep_kernel<<<dim3(256 + 384, 2), 256>>>(atoms, amino, Wcc, Wcp);
    biatt_gemm_kernel<<<NPERS, 512, SM_TOT>>>(bcc, bcp, out);
}

// round 13
// speedup vs baseline: 1.4748x; 1.0110x over previous
#include <cuda_runtime.h>
#include <cuda_bf16.h>
#include <cuda_fp16.h>
#include <cstdint>

// BiATT algebraic collapse: softmax over axis=1 of a [N,1] tensor == 1.0, so
// all four bi-attention branches are identity. cf = atoms @ (sum Wcc blocks) + bcc,
// pf = amino @ (sum Wcp blocks) + bcp  =>  two [6144x512]@[512x512] GEMMs.
// Single fp16 GEMM (fp32 accum), rel_err 2.93e-4 (stable since R7).
// R13: barrier-free mainloop — full/empty mbarrier ring (producer = lane 0 of
// warp 0, consumers arrive per warp). No __syncthreads in the chunk stream;
// warps decouple up to 2 chunks; epilogue overlaps other warps' MMAs.

#define DIM     512
#define M_ROWS  6144
#define BM      128
#define BN      128
#define BK      64
#define NCHUNK  (DIM / BK)     // 8 per tile
#define NTILES  384            // 4 nblk x 48 mblk x 2 z
#define NPERS   296            // persistent CTAs = 148 SMs x occ 2
#define BLKB    16384          // 16KB block: 128 rows x 64 fp16, swizzled
#define NWARP   16

// tile-blocked, pre-swizzled fp16 operands (uint4 => 16B-aligned for bulk copy)
__device__ uint4 g_A4[2 * 48 * 8 * (BLKB / 16)];   // [z][mtile][chunk][16KB]
__device__ uint4 g_W4[2 * 4 * 8 * (BLKB / 16)];    // [z][ntile][chunk][16KB]

// ---- smem: 3 stages x (A 16KB + B 16KB); 6 mbarriers
#define SM_A      0
#define SM_B      16384
#define SM_STAGE  32768
#define SM_MBAR   (3 * SM_STAGE)        // 98304: full[3] then empty[3]
#define SM_TOT    (SM_MBAR + 64)        // 98368 dynamic (occ 2)

// ---------------------------------------------------------------- helpers
__device__ __forceinline__ uint32_t smem_u32(const void* p) {
    return (uint32_t)__cvta_generic_to_shared(p);
}
__device__ __forceinline__ uint32_t sw128(uint32_t off) {
    return off ^ ((off >> 3) & 0x70);
}
__device__ __forceinline__ void bulk_cp(uint32_t dst, const void* src,
                                        uint32_t bytes, uint32_t mbar) {
    asm volatile(
        "cp.async.bulk.shared::cluster.global.mbarrier::complete_tx::bytes "
        "[%0], [%1], %2, [%3];"
        :: "r"(dst), "l"(src), "r"(bytes), "r"(mbar) : "memory");
}
__device__ __forceinline__ void mbar_init(uint32_t mbar, uint32_t cnt) {
    asm volatile("mbarrier.init.shared.b64 [%0], %1;" :: "r"(mbar), "r"(cnt)
                 : "memory");
}
__device__ __forceinline__ void mbar_expect(uint32_t mbar, uint32_t tx) {
    asm volatile("mbarrier.arrive.expect_tx.shared.b64 _, [%0], %1;"
                 :: "r"(mbar), "r"(tx) : "memory");
}
__device__ __forceinline__ void mbar_arrive(uint32_t mbar) {
    asm volatile("mbarrier.arrive.shared.b64 _, [%0];" :: "r"(mbar) : "memory");
}
__device__ __forceinline__ void mbar_wait(uint32_t mbar, uint32_t parity) {
    asm volatile(
        "{\n\t.reg .pred P1;\n\t"
        "WAIT_LOOP_%=:\n\t"
        "mbarrier.try_wait.parity.acquire.cta.shared::cta.b64 P1, [%0], %1, 0x989680;\n\t"
        "@P1 bra.uni WAIT_DONE_%=;\n\t"
        "bra.uni WAIT_LOOP_%=;\n\t"
        "WAIT_DONE_%=:\n\t}"
        :: "r"(mbar), "r"(parity) : "memory");
}
__device__ __forceinline__ void ldsm_x4(uint32_t* r, uint32_t addr) {
    asm volatile("ldmatrix.sync.aligned.m8n8.x4.shared.b16 {%0,%1,%2,%3}, [%4];"
                 : "=r"(r[0]), "=r"(r[1]), "=r"(r[2]), "=r"(r[3]) : "r"(addr));
}
__device__ __forceinline__ void mma_f16(float* d, const uint32_t* a,
                                        uint32_t b0, uint32_t b1) {
    asm volatile(
        "mma.sync.aligned.m16n8k16.row.col.f32.f16.f16.f32 "
        "{%0,%1,%2,%3}, {%4,%5,%6,%7}, {%8,%9}, {%0,%1,%2,%3};"
        : "+f"(d[0]), "+f"(d[1]), "+f"(d[2]), "+f"(d[3])
        : "r"(a[0]), "r"(a[1]), "r"(a[2]), "r"(a[3]), "r"(b0), "r"(b1));
}

// ---------------------------- fused prologue: fold-W + convert-A, blocked+swizzled
// grid (256 + 384, 2):  x<256 fold-W,  x>=256 convert-A  (unchanged from R12)
__global__ void __launch_bounds__(256)
prep_kernel(const float* __restrict__ atoms, const float* __restrict__ amino,
            const float* __restrict__ Wcc,   const float* __restrict__ Wcp) {
    const int z   = blockIdx.y;
    const int tid = threadIdx.x;
    char* gA = reinterpret_cast<char*>(g_A4);
    char* gW = reinterpret_cast<char*>(g_W4);

    if (blockIdx.x < 256) {
        __shared__ float s[32][33];
        const float* __restrict__ W = z ? Wcp : Wcc;
        const int nb = blockIdx.x & 15;
        const int kb = blockIdx.x >> 4;
        const int n0 = nb * 32;
        const int k0 = kb * 32;
        const int tx = tid & 31;
        const int ty = tid >> 5;
        float v[4] = {0.f, 0.f, 0.f, 0.f};
#pragma unroll
        for (int b = 0; b < 4; b++) {
#pragma unroll
            for (int i = 0; i < 4; i++) {
                const int k = k0 + ty + i * 8;
                v[i] += W[(size_t)(b * DIM + k) * DIM + n0 + tx];
            }
        }
#pragma unroll
        for (int i = 0; i < 4; i++) s[tx][ty + i * 8] = v[i];
        __syncthreads();
#pragma unroll
        for (int i = 0; i < 4; i++) {
            const int n2 = n0 + ty + i * 8;
            const int k2 = k0 + tx;
            const int ntile = n2 >> 7;
            const int c     = k2 >> 6;
            const size_t base = (size_t)(((z * 4 + ntile) * 8 + c)) * BLKB;
            const uint32_t off = sw128((uint32_t)((n2 & 127) * 128 + (k2 & 63) * 2));
            *reinterpret_cast<__half*>(gW + base + off) =
                __float2half_rn(s[ty + i * 8][tx]);
        }
    } else {
        const float* __restrict__ X = z ? amino : atoms;
        const int cb = blockIdx.x - 256;
        const int m  = cb >> 3;
        const int c  = cb & 7;
        float4 v[8];
        int   rows[8], cols[8];
#pragma unroll
        for (int it = 0; it < 8; it++) {
            const int gidx = it * 1024 + tid * 4;
            rows[it] = gidx >> 6;
            cols[it] = gidx & 63;
            v[it] = *reinterpret_cast<const float4*>(
                &X[(size_t)(m * 128 + rows[it]) * DIM + c * 64 + cols[it]]);
        }
        char* dst = gA + (size_t)((z * 48 + m) * 8 + c) * BLKB;
#pragma unroll
        for (int it = 0; it < 8; it++) {
            __half2 h0 = __floats2half2_rn(v[it].x, v[it].y);
            __half2 h1 = __floats2half2_rn(v[it].z, v[it].w);
            uint2 o = make_uint2(*reinterpret_cast<uint32_t*>(&h0),
                                 *reinterpret_cast<uint32_t*>(&h1));
            const uint32_t off =
                sw128((uint32_t)(rows[it] * 128 + cols[it] * 2));
            *reinterpret_cast<uint2*>(dst + off) = o;
        }
    }
}

// --------------------------------------------------- persistent HMMA GEMM
// grid 296, 512 threads (16 warps, warp tile 32x32); barrier-free ring pipe
__global__ void __launch_bounds__(512, 2)
biatt_gemm_kernel(const float* __restrict__ bcc,
                  const float* __restrict__ bcp,
                  float* __restrict__ out) {
    extern __shared__ __align__(16) char sm[];
    const uint32_t sbase = smem_u32(sm);

    const int tid  = threadIdx.x;
    const int wid  = tid >> 5;
    const int lane = tid & 31;
    const int mw   = (wid >> 2) * 32;
    const int nw   = (wid & 3) * 32;
    const char* gA = reinterpret_cast<const char*>(g_A4);
    const char* gW = reinterpret_cast<const char*>(g_W4);

    // ldmatrix lane constants (swizzled rows of 128B, XOR (R&7)<<4)
    const int      Ra    = mw + (lane & 15);
    const uint32_t rowA  = (uint32_t)Ra * 128;
    const uint32_t xA    = (uint32_t)((Ra & 7) << 4);
    const uint32_t colA0 = (uint32_t)((lane >> 4) << 4);
    const int      Rb    = nw + ((lane >> 4) << 3) + (lane & 7);
    const uint32_t rowB  = (uint32_t)Rb * 128;
    const uint32_t xB    = (uint32_t)((Rb & 7) << 4);
    const uint32_t colB0 = (uint32_t)(((lane >> 3) & 1) << 4);

    const uint32_t fullB  = sbase + SM_MBAR;        // full[s]  at +8s
    const uint32_t emptyB = sbase + SM_MBAR + 24;   // empty[s] at +8s

    if (tid == 0) {
#pragma unroll
        for (int s = 0; s < 3; ++s) {
            mbar_init(fullB  + s * 8, 1);
            mbar_init(emptyB + s * 8, NWARP);
        }
    }
    __syncthreads();   // only CTA-wide barrier in the kernel

    const int ntiles  = (blockIdx.x + NPERS < NTILES) ? 2 : 1;
    const int nchunks = ntiles * NCHUNK;

    // ---- producer prologue: chunks 0,1 of tile 0 into stages 0,1
    if (tid == 0) {
        const int t0  = blockIdx.x;
        const int z   = t0 / 192;
        const int rem = t0 - z * 192;
        const char* sA = gA + (size_t)((z * 48 + (rem >> 2)) * 8) * BLKB;
        const char* sB = gW + (size_t)((z * 4  + (rem & 3))  * 8) * BLKB;
#pragma unroll
        for (int p = 0; p < 2; ++p) {
            const uint32_t st = sbase + (uint32_t)(p * SM_STAGE);
            mbar_expect(fullB + p * 8, 2 * BLKB);
            bulk_cp(st + SM_A, sA + (size_t)p * BLKB, BLKB, fullB + p * 8);
            bulk_cp(st + SM_B, sB + (size_t)p * BLKB, BLKB, fullB + p * 8);
        }
    }

    float acc[2][4][4];
#pragma unroll
    for (int i = 0; i < 2; i++)
#pragma unroll
        for (int j = 0; j < 4; j++)
#pragma unroll
            for (int e = 0; e < 4; e++) acc[i][j][e] = 0.f;

    uint32_t fpm = 0;   // consumer parity per stage
    uint32_t epm = 0;   // producer (empty) parity per stage

    for (int g = 0; g < nchunks; ++g) {
        const int s = g % 3;

        // ---- producer: refill stage (g+2)%3 with chunk g+2
        if (tid == 0 && g + 2 < nchunks) {
            const int gg = g + 2;
            const int s2 = gg % 3;
            if (gg >= 3) {   // stage reused: wait all 16 warps drained prior use
                mbar_wait(emptyB + s2 * 8, (epm >> s2) & 1u);
                epm ^= 1u << s2;
            }
            const int t   = blockIdx.x + (gg >> 3) * NPERS;
            const int z   = t / 192;
            const int rem = t - z * 192;
            const int c   = gg & 7;
            const char* sA = gA + (size_t)((z * 48 + (rem >> 2)) * 8 + c) * BLKB;
            const char* sB = gW + (size_t)((z * 4  + (rem & 3))  * 8 + c) * BLKB;
            const uint32_t st = sbase + (uint32_t)(s2 * SM_STAGE);
            mbar_expect(fullB + s2 * 8, 2 * BLKB);
            bulk_cp(st + SM_A, sA, BLKB, fullB + s2 * 8);
            bulk_cp(st + SM_B, sB, BLKB, fullB + s2 * 8);
        }

        // ---- consumer: wait data, compute
        mbar_wait(fullB + s * 8, (fpm >> s) & 1u);
        fpm ^= 1u << s;

        const uint32_t stb = sbase + (uint32_t)(s * SM_STAGE);
        const uint32_t aBase = stb + SM_A + rowA;
        const uint32_t bBase = stb + SM_B + rowB;
#pragma unroll
        for (int ks = 0; ks < 4; ++ks) {
            const uint32_t cb = (uint32_t)(ks * 32);
            const uint32_t aCol = (colA0 + cb) ^ xA;
            const uint32_t bCol = (colB0 + cb) ^ xB;
            uint32_t af[2][4];
#pragma unroll
            for (int mt = 0; mt < 2; ++mt)
                ldsm_x4(af[mt], aBase + mt * 2048 + aCol);
#pragma unroll
            for (int j2 = 0; j2 < 2; ++j2) {
                uint32_t bf[4];
                ldsm_x4(bf, bBase + j2 * 2048 + bCol);
#pragma unroll
                for (int mt = 0; mt < 2; ++mt) {
                    mma_f16(acc[mt][j2 * 2],     af[mt], bf[0], bf[1]);
                    mma_f16(acc[mt][j2 * 2 + 1], af[mt], bf[2], bf[3]);
                }
            }
        }
        if (lane == 0) mbar_arrive(emptyB + s * 8);   // stage drained (this warp)

        // ---- per-warp epilogue at tile end (overlaps other warps' compute)
        if ((g & 7) == 7) {
            const int t   = blockIdx.x + (g >> 3) * NPERS;
            const int z   = t / 192;
            const int rem = t - z * 192;
            const int n0  = (rem & 3) * BN;
            const int m0  = (rem >> 2) * BM;
            const float* __restrict__ bias = (z ? bcp : bcc) + n0;
            float* C = out + (size_t)z * M_ROWS * DIM + (size_t)m0 * DIM + n0;
#pragma unroll
            for (int mt = 0; mt < 2; ++mt) {
                const int r0 = mw + mt * 16 + (lane >> 2);
#pragma unroll
                for (int nt = 0; nt < 4; ++nt) {
                    const int cl = nw + nt * 8 + (lane & 3) * 2;
                    const float2 bv = __ldg(reinterpret_cast<const float2*>(bias + cl));
                    float2 v0 = make_float2(acc[mt][nt][0] + bv.x,
                                            acc[mt][nt][1] + bv.y);
                    float2 v1 = make_float2(acc[mt][nt][2] + bv.x,
                                            acc[mt][nt][3] + bv.y);
                    *reinterpret_cast<float2*>(&C[(size_t)r0 * DIM + cl]) = v0;
                    *reinterpret_cast<float2*>(&C[(size_t)(r0 + 8) * DIM + cl]) = v1;
                    acc[mt][nt][0] = 0.f; acc[mt][nt][1] = 0.f;
                    acc[mt][nt][2] = 0.f; acc[mt][nt][3] = 0.f;
                }
            }
        }
    }
}

// ------------------------------------------------------------------ launch
extern "C" void kernel_launch(void* const* d_in, const int* in_sizes, int n_in,
                              void* d_out, int out_size) {
    const float* atoms = (const float*)d_in[0];
    const float* amino = (const float*)d_in[1];
    const float* Wcc   = (const float*)d_in[15];
    const float* bcc   = (const float*)d_in[16];
    const float* Wcp   = (const float*)d_in[17];
    const float* bcp   = (const float*)d_in[18];
    float* out = (float*)d_out;

    static bool attr_set = false;
    if (!attr_set) {
        cudaFuncSetAttribute(biatt_gemm_kernel,
                             cudaFuncAttributeMaxDynamicSharedMemorySize, SM_TOT);
        attr_set = true;
    }

    prep_kernel<<<dim3(256 + 384, 2), 256>>>(atoms, amino, Wcc, Wcp);
    biatt_gemm_kernel<<<NPERS, 512, SM_TOT>>>(bcc, bcp, out);
}

// round 14
// speedup vs baseline: 1.5731x; 1.0667x over previous
#include <cuda_runtime.h>
#include <cuda_bf16.h>
#include <cuda_fp16.h>
#include <cstdint>

// BiATT algebraic collapse: softmax over axis=1 of a [N,1] tensor == 1.0, so
// all four bi-attention branches are identity. cf = atoms @ (sum Wcc blocks) + bcc,
// pf = amino @ (sum Wcp blocks) + bcp  =>  two [6144x512]@[512x512] GEMMs.
// Single fp16 GEMM (fp32 accum), rel_err 2.93e-4 (stable since R7).
// R14: GEMM was SMEM-CROSSBAR-bound (LDSM redundancy 4x with 32x32 warp tiles:
// 128KB smem reads per 32KB tile). Warp tile 64x64, 4 warps/CTA, 128 thr:
// halves LDSM traffic -> tensor pipe becomes the binding resource.

#define DIM     512
#define M_ROWS  6144
#define BM      128
#define BN      128
#define BK      64
#define NCHUNK  (DIM / BK)     // 8 per tile
#define NTILES  384            // 4 nblk x 48 mblk x 2 z
#define NPERS   296            // persistent CTAs = 148 SMs x occ 2
#define BLKB    16384          // 16KB block: 128 rows x 64 fp16, swizzled
#define NWARP   4

// tile-blocked, pre-swizzled fp16 operands (uint4 => 16B-aligned for bulk copy)
__device__ uint4 g_A4[2 * 48 * 8 * (BLKB / 16)];   // [z][mtile][chunk][16KB]
__device__ uint4 g_W4[2 * 4 * 8 * (BLKB / 16)];    // [z][ntile][chunk][16KB]

// ---- smem: 3 stages x (A 16KB + B 16KB); 6 mbarriers
#define SM_A      0
#define SM_B      16384
#define SM_STAGE  32768
#define SM_MBAR   (3 * SM_STAGE)        // 98304: full[3] then empty[3]
#define SM_TOT    (SM_MBAR + 64)        // 98368 dynamic (occ 2)

// ---------------------------------------------------------------- helpers
__device__ __forceinline__ uint32_t smem_u32(const void* p) {
    return (uint32_t)__cvta_generic_to_shared(p);
}
__device__ __forceinline__ uint32_t sw128(uint32_t off) {
    return off ^ ((off >> 3) & 0x70);
}
__device__ __forceinline__ void bulk_cp(uint32_t dst, const void* src,
                                        uint32_t bytes, uint32_t mbar) {
    asm volatile(
        "cp.async.bulk.shared::cluster.global.mbarrier::complete_tx::bytes "
        "[%0], [%1], %2, [%3];"
        :: "r"(dst), "l"(src), "r"(bytes), "r"(mbar) : "memory");
}
__device__ __forceinline__ void mbar_init(uint32_t mbar, uint32_t cnt) {
    asm volatile("mbarrier.init.shared.b64 [%0], %1;" :: "r"(mbar), "r"(cnt)
                 : "memory");
}
__device__ __forceinline__ void mbar_expect(uint32_t mbar, uint32_t tx) {
    asm volatile("mbarrier.arrive.expect_tx.shared.b64 _, [%0], %1;"
                 :: "r"(mbar), "r"(tx) : "memory");
}
__device__ __forceinline__ void mbar_arrive(uint32_t mbar) {
    asm volatile("mbarrier.arrive.shared.b64 _, [%0];" :: "r"(mbar) : "memory");
}
__device__ __forceinline__ void mbar_wait(uint32_t mbar, uint32_t parity) {
    asm volatile(
        "{\n\t.reg .pred P1;\n\t"
        "WAIT_LOOP_%=:\n\t"
        "mbarrier.try_wait.parity.acquire.cta.shared::cta.b64 P1, [%0], %1, 0x989680;\n\t"
        "@P1 bra.uni WAIT_DONE_%=;\n\t"
        "bra.uni WAIT_LOOP_%=;\n\t"
        "WAIT_DONE_%=:\n\t}"
        :: "r"(mbar), "r"(parity) : "memory");
}
__device__ __forceinline__ void ldsm_x4(uint32_t* r, uint32_t addr) {
    asm volatile("ldmatrix.sync.aligned.m8n8.x4.shared.b16 {%0,%1,%2,%3}, [%4];"
                 : "=r"(r[0]), "=r"(r[1]), "=r"(r[2]), "=r"(r[3]) : "r"(addr));
}
__device__ __forceinline__ void mma_f16(float* d, const uint32_t* a,
                                        uint32_t b0, uint32_t b1) {
    asm volatile(
        "mma.sync.aligned.m16n8k16.row.col.f32.f16.f16.f32 "
        "{%0,%1,%2,%3}, {%4,%5,%6,%7}, {%8,%9}, {%0,%1,%2,%3};"
        : "+f"(d[0]), "+f"(d[1]), "+f"(d[2]), "+f"(d[3])
        : "r"(a[0]), "r"(a[1]), "r"(a[2]), "r"(a[3]), "r"(b0), "r"(b1));
}

// ---------------------------- fused prologue: fold-W + convert-A, blocked+swizzled
// grid (256 + 384, 2):  x<256 fold-W,  x>=256 convert-A  (unchanged from R12)
__global__ void __launch_bounds__(256)
prep_kernel(const float* __restrict__ atoms, const float* __restrict__ amino,
            const float* __restrict__ Wcc,   const float* __restrict__ Wcp) {
    const int z   = blockIdx.y;
    const int tid = threadIdx.x;
    char* gA = reinterpret_cast<char*>(g_A4);
    char* gW = reinterpret_cast<char*>(g_W4);

    if (blockIdx.x < 256) {
        __shared__ float s[32][33];
        const float* __restrict__ W = z ? Wcp : Wcc;
        const int nb = blockIdx.x & 15;
        const int kb = blockIdx.x >> 4;
        const int n0 = nb * 32;
        const int k0 = kb * 32;
        const int tx = tid & 31;
        const int ty = tid >> 5;
        float v[4] = {0.f, 0.f, 0.f, 0.f};
#pragma unroll
        for (int b = 0; b < 4; b++) {
#pragma unroll
            for (int i = 0; i < 4; i++) {
                const int k = k0 + ty + i * 8;
                v[i] += W[(size_t)(b * DIM + k) * DIM + n0 + tx];
            }
        }
#pragma unroll
        for (int i = 0; i < 4; i++) s[tx][ty + i * 8] = v[i];
        __syncthreads();
#pragma unroll
        for (int i = 0; i < 4; i++) {
            const int n2 = n0 + ty + i * 8;
            const int k2 = k0 + tx;
            const int ntile = n2 >> 7;
            const int c     = k2 >> 6;
            const size_t base = (size_t)(((z * 4 + ntile) * 8 + c)) * BLKB;
            const uint32_t off = sw128((uint32_t)((n2 & 127) * 128 + (k2 & 63) * 2));
            *reinterpret_cast<__half*>(gW + base + off) =
                __float2half_rn(s[ty + i * 8][tx]);
        }
    } else {
        const float* __restrict__ X = z ? amino : atoms;
        const int cb = blockIdx.x - 256;
        const int m  = cb >> 3;
        const int c  = cb & 7;
        float4 v[8];
        int   rows[8], cols[8];
#pragma unroll
        for (int it = 0; it < 8; it++) {
            const int gidx = it * 1024 + tid * 4;
            rows[it] = gidx >> 6;
            cols[it] = gidx & 63;
            v[it] = *reinterpret_cast<const float4*>(
                &X[(size_t)(m * 128 + rows[it]) * DIM + c * 64 + cols[it]]);
        }
        char* dst = gA + (size_t)((z * 48 + m) * 8 + c) * BLKB;
#pragma unroll
        for (int it = 0; it < 8; it++) {
            __half2 h0 = __floats2half2_rn(v[it].x, v[it].y);
            __half2 h1 = __floats2half2_rn(v[it].z, v[it].w);
            uint2 o = make_uint2(*reinterpret_cast<uint32_t*>(&h0),
                                 *reinterpret_cast<uint32_t*>(&h1));
            const uint32_t off =
                sw128((uint32_t)(rows[it] * 128 + cols[it] * 2));
            *reinterpret_cast<uint2*>(dst + off) = o;
        }
    }
}

// --------------------------------------------------- persistent HMMA GEMM
// grid 296, 128 threads (4 warps, warp tile 64x64); barrier-free ring pipe
__global__ void __launch_bounds__(128, 2)
biatt_gemm_kernel(const float* __restrict__ bcc,
                  const float* __restrict__ bcp,
                  float* __restrict__ out) {
    extern __shared__ __align__(16) char sm[];
    const uint32_t sbase = smem_u32(sm);

    const int tid  = threadIdx.x;
    const int wid  = tid >> 5;
    const int lane = tid & 31;
    const int mw   = (wid >> 1) * 64;     // warp m offset (0 or 64)
    const int nw   = (wid & 1) * 64;      // warp n offset (0 or 64)
    const char* gA = reinterpret_cast<const char*>(g_A4);
    const char* gW = reinterpret_cast<const char*>(g_W4);

    // ldmatrix lane constants (swizzled rows of 128B, XOR (R&7)<<4).
    // mt/j2 row offsets are multiples of 16, so the XOR mask is lane-constant.
    const uint32_t rowA  = (uint32_t)(mw + (lane & 15)) * 128;
    const uint32_t xA    = (uint32_t)(((lane & 15) & 7) << 4);
    const uint32_t colA0 = (uint32_t)((lane >> 4) << 4);
    const uint32_t rowB  = (uint32_t)(nw + ((lane >> 4) << 3) + (lane & 7)) * 128;
    const uint32_t xB    = (uint32_t)((lane & 7) << 4);
    const uint32_t colB0 = (uint32_t)(((lane >> 3) & 1) << 4);

    const uint32_t fullB  = sbase + SM_MBAR;        // full[s]  at +8s
    const uint32_t emptyB = sbase + SM_MBAR + 24;   // empty[s] at +8s

    if (tid == 0) {
#pragma unroll
        for (int s = 0; s < 3; ++s) {
            mbar_init(fullB  + s * 8, 1);
            mbar_init(emptyB + s * 8, NWARP);
        }
    }
    __syncthreads();   // only CTA-wide barrier in the kernel

    const int ntiles  = (blockIdx.x + NPERS < NTILES) ? 2 : 1;
    const int nchunks = ntiles * NCHUNK;

    // ---- producer prologue: chunks 0,1 of tile 0 into stages 0,1
    if (tid == 0) {
        const int t0  = blockIdx.x;
        const int z   = t0 / 192;
        const int rem = t0 - z * 192;
        const char* sA = gA + (size_t)((z * 48 + (rem >> 2)) * 8) * BLKB;
        const char* sB = gW + (size_t)((z * 4  + (rem & 3))  * 8) * BLKB;
#pragma unroll
        for (int p = 0; p < 2; ++p) {
            const uint32_t st = sbase + (uint32_t)(p * SM_STAGE);
            mbar_expect(fullB + p * 8, 2 * BLKB);
            bulk_cp(st + SM_A, sA + (size_t)p * BLKB, BLKB, fullB + p * 8);
            bulk_cp(st + SM_B, sB + (size_t)p * BLKB, BLKB, fullB + p * 8);
        }
    }

    float acc[4][8][4];
#pragma unroll
    for (int i = 0; i < 4; i++)
#pragma unroll
        for (int j = 0; j < 8; j++)
#pragma unroll
            for (int e = 0; e < 4; e++) acc[i][j][e] = 0.f;

    uint32_t fpm = 0;   // consumer parity per stage
    uint32_t epm = 0;   // producer (empty) parity per stage

    for (int g = 0; g < nchunks; ++g) {
        const int s = g % 3;

        // ---- producer: refill stage (g+2)%3 with chunk g+2
        if (tid == 0 && g + 2 < nchunks) {
            const int gg = g + 2;
            const int s2 = gg % 3;
            if (gg >= 3) {   // stage reused: wait all 4 warps drained prior use
                mbar_wait(emptyB + s2 * 8, (epm >> s2) & 1u);
                epm ^= 1u << s2;
            }
            const int t   = blockIdx.x + (gg >> 3) * NPERS;
            const int z   = t / 192;
            const int rem = t - z * 192;
            const int c   = gg & 7;
            const char* sA = gA + (size_t)((z * 48 + (rem >> 2)) * 8 + c) * BLKB;
            const char* sB = gW + (size_t)((z * 4  + (rem & 3))  * 8 + c) * BLKB;
            const uint32_t st = sbase + (uint32_t)(s2 * SM_STAGE);
            mbar_expect(fullB + s2 * 8, 2 * BLKB);
            bulk_cp(st + SM_A, sA, BLKB, fullB + s2 * 8);
            bulk_cp(st + SM_B, sB, BLKB, fullB + s2 * 8);
        }

        // ---- consumer: wait data, compute
        mbar_wait(fullB + s * 8, (fpm >> s) & 1u);
        fpm ^= 1u << s;

        const uint32_t stb = sbase + (uint32_t)(s * SM_STAGE);
        const uint32_t aBase = stb + SM_A + rowA;
        const uint32_t bBase = stb + SM_B + rowB;
#pragma unroll
        for (int ks = 0; ks < 4; ++ks) {
            const uint32_t cb = (uint32_t)(ks * 32);
            const uint32_t aCol = (colA0 + cb) ^ xA;
            const uint32_t bCol = (colB0 + cb) ^ xB;
            uint32_t af[4][4];
#pragma unroll
            for (int mt = 0; mt < 4; ++mt)
                ldsm_x4(af[mt], aBase + mt * 2048 + aCol);
#pragma unroll
            for (int j2 = 0; j2 < 4; ++j2) {
                uint32_t bf[4];
                ldsm_x4(bf, bBase + j2 * 2048 + bCol);
#pragma unroll
                for (int mt = 0; mt < 4; ++mt) {
                    mma_f16(acc[mt][j2 * 2],     af[mt], bf[0], bf[1]);
                    mma_f16(acc[mt][j2 * 2 + 1], af[mt], bf[2], bf[3]);
                }
            }
        }
        if (lane == 0) mbar_arrive(emptyB + s * 8);   // stage drained (this warp)

        // ---- per-warp epilogue at tile end (overlaps other warps' compute)
        if ((g & 7) == 7) {
            const int t   = blockIdx.x + (g >> 3) * NPERS;
            const int z   = t / 192;
            const int rem = t - z * 192;
            const int n0  = (rem & 3) * BN;
            const int m0  = (rem >> 2) * BM;
            const float* __restrict__ bias = (z ? bcp : bcc) + n0;
            float* C = out + (size_t)z * M_ROWS * DIM + (size_t)m0 * DIM + n0;
#pragma unroll
            for (int mt = 0; mt < 4; ++mt) {
                const int r0 = mw + mt * 16 + (lane >> 2);
#pragma unroll
                for (int nt = 0; nt < 8; ++nt) {
                    const int cl = nw + nt * 8 + (lane & 3) * 2;
                    const float2 bv = __ldg(reinterpret_cast<const float2*>(bias + cl));
                    float2 v0 = make_float2(acc[mt][nt][0] + bv.x,
                                            acc[mt][nt][1] + bv.y);
                    float2 v1 = make_float2(acc[mt][nt][2] + bv.x,
                                            acc[mt][nt][3] + bv.y);
                    *reinterpret_cast<float2*>(&C[(size_t)r0 * DIM + cl]) = v0;
                    *reinterpret_cast<float2*>(&C[(size_t)(r0 + 8) * DIM + cl]) = v1;
                    acc[mt][nt][0] = 0.f; acc[mt][nt][1] = 0.f;
                    acc[mt][nt][2] = 0.f; acc[mt][nt][3] = 0.f;
                }
            }
        }
    }
}

// ------------------------------------------------------------------ launch
extern "C" void kernel_launch(void* const* d_in, const int* in_sizes, int n_in,
                              void* d_out, int out_size) {
    const float* atoms = (const float*)d_in[0];
    const float* amino = (const float*)d_in[1];
    const float* Wcc   = (const float*)d_in[15];
    const float* bcc   = (const float*)d_in[16];
    const float* Wcp   = (const float*)d_in[17];
    const float* bcp   = (const float*)d_in[18];
    float* out = (float*)d_out;

    static bool attr_set = false;
    if (!attr_set) {
        cudaFuncSetAttribute(biatt_gemm_kernel,
                             cudaFuncAttributeMaxDynamicSharedMemorySize, SM_TOT);
        attr_set = true;
    }

    prep_kernel<<<dim3(256 + 384, 2), 256>>>(atoms, amino, Wcc, Wcp);
    biatt_gemm_kernel<<<NPERS, 128, SM_TOT>>>(bcc, bcp, out);
}

// round 15
// speedup vs baseline: 1.5880x; 1.0094x over previous
#include <cuda_runtime.h>
#include <cuda_bf16.h>
#include <cuda_fp16.h>
#include <cstdint>

// BiATT algebraic collapse: softmax over axis=1 of a [N,1] tensor == 1.0, so
// all four bi-attention branches are identity. cf = atoms @ (sum Wcc blocks) + bcc,
// pf = amino @ (sum Wcp blocks) + bcp  =>  two [6144x512]@[512x512] GEMMs.
// Single fp16 GEMM (fp32 accum), rel_err 2.93e-4 (stable since R7).
// R15: 8 warps x (64x32) warp tiles — the measured optimum between R13
// (16 warps: hiding but 4x smem redundancy) and R14 (4 warps: 2x redundancy
// but only 2 warps/SMSP). 4 warps/SMSP at occ 2, 3x redundancy; smem floor
// ~= tensor floor.

#define DIM     512
#define M_ROWS  6144
#define BM      128
#define BN      128
#define BK      64
#define NCHUNK  (DIM / BK)     // 8 per tile
#define NTILES  384            // 4 nblk x 48 mblk x 2 z
#define NPERS   296            // persistent CTAs = 148 SMs x occ 2
#define BLKB    16384          // 16KB block: 128 rows x 64 fp16, swizzled
#define NWARP   8

// tile-blocked, pre-swizzled fp16 operands (uint4 => 16B-aligned for bulk copy)
__device__ uint4 g_A4[2 * 48 * 8 * (BLKB / 16)];   // [z][mtile][chunk][16KB]
__device__ uint4 g_W4[2 * 4 * 8 * (BLKB / 16)];    // [z][ntile][chunk][16KB]

// ---- smem: 3 stages x (A 16KB + B 16KB); 6 mbarriers
#define SM_A      0
#define SM_B      16384
#define SM_STAGE  32768
#define SM_MBAR   (3 * SM_STAGE)        // 98304: full[3] then empty[3]
#define SM_TOT    (SM_MBAR + 64)        // 98368 dynamic (occ 2)

// ---------------------------------------------------------------- helpers
__device__ __forceinline__ uint32_t smem_u32(const void* p) {
    return (uint32_t)__cvta_generic_to_shared(p);
}
__device__ __forceinline__ uint32_t sw128(uint32_t off) {
    return off ^ ((off >> 3) & 0x70);
}
__device__ __forceinline__ void bulk_cp(uint32_t dst, const void* src,
                                        uint32_t bytes, uint32_t mbar) {
    asm volatile(
        "cp.async.bulk.shared::cluster.global.mbarrier::complete_tx::bytes "
        "[%0], [%1], %2, [%3];"
        :: "r"(dst), "l"(src), "r"(bytes), "r"(mbar) : "memory");
}
__device__ __forceinline__ void mbar_init(uint32_t mbar, uint32_t cnt) {
    asm volatile("mbarrier.init.shared.b64 [%0], %1;" :: "r"(mbar), "r"(cnt)
                 : "memory");
}
__device__ __forceinline__ void mbar_expect(uint32_t mbar, uint32_t tx) {
    asm volatile("mbarrier.arrive.expect_tx.shared.b64 _, [%0], %1;"
                 :: "r"(mbar), "r"(tx) : "memory");
}
__device__ __forceinline__ void mbar_arrive(uint32_t mbar) {
    asm volatile("mbarrier.arrive.shared.b64 _, [%0];" :: "r"(mbar) : "memory");
}
__device__ __forceinline__ void mbar_wait(uint32_t mbar, uint32_t parity) {
    asm volatile(
        "{\n\t.reg .pred P1;\n\t"
        "WAIT_LOOP_%=:\n\t"
        "mbarrier.try_wait.parity.acquire.cta.shared::cta.b64 P1, [%0], %1, 0x989680;\n\t"
        "@P1 bra.uni WAIT_DONE_%=;\n\t"
        "bra.uni WAIT_LOOP_%=;\n\t"
        "WAIT_DONE_%=:\n\t}"
        :: "r"(mbar), "r"(parity) : "memory");
}
__device__ __forceinline__ void ldsm_x4(uint32_t* r, uint32_t addr) {
    asm volatile("ldmatrix.sync.aligned.m8n8.x4.shared.b16 {%0,%1,%2,%3}, [%4];"
                 : "=r"(r[0]), "=r"(r[1]), "=r"(r[2]), "=r"(r[3]) : "r"(addr));
}
__device__ __forceinline__ void mma_f16(float* d, const uint32_t* a,
                                        uint32_t b0, uint32_t b1) {
    asm volatile(
        "mma.sync.aligned.m16n8k16.row.col.f32.f16.f16.f32 "
        "{%0,%1,%2,%3}, {%4,%5,%6,%7}, {%8,%9}, {%0,%1,%2,%3};"
        : "+f"(d[0]), "+f"(d[1]), "+f"(d[2]), "+f"(d[3])
        : "r"(a[0]), "r"(a[1]), "r"(a[2]), "r"(a[3]), "r"(b0), "r"(b1));
}

// ---------------------------- fused prologue: fold-W + convert-A, blocked+swizzled
// grid (256 + 384, 2):  x<256 fold-W,  x>=256 convert-A  (unchanged from R12)
__global__ void __launch_bounds__(256)
prep_kernel(const float* __restrict__ atoms, const float* __restrict__ amino,
            const float* __restrict__ Wcc,   const float* __restrict__ Wcp) {
    const int z   = blockIdx.y;
    const int tid = threadIdx.x;
    char* gA = reinterpret_cast<char*>(g_A4);
    char* gW = reinterpret_cast<char*>(g_W4);

    if (blockIdx.x < 256) {
        __shared__ float s[32][33];
        const float* __restrict__ W = z ? Wcp : Wcc;
        const int nb = blockIdx.x & 15;
        const int kb = blockIdx.x >> 4;
        const int n0 = nb * 32;
        const int k0 = kb * 32;
        const int tx = tid & 31;
        const int ty = tid >> 5;
        float v[4] = {0.f, 0.f, 0.f, 0.f};
#pragma unroll
        for (int b = 0; b < 4; b++) {
#pragma unroll
            for (int i = 0; i < 4; i++) {
                const int k = k0 + ty + i * 8;
                v[i] += W[(size_t)(b * DIM + k) * DIM + n0 + tx];
            }
        }
#pragma unroll
        for (int i = 0; i < 4; i++) s[tx][ty + i * 8] = v[i];
        __syncthreads();
#pragma unroll
        for (int i = 0; i < 4; i++) {
            const int n2 = n0 + ty + i * 8;
            const int k2 = k0 + tx;
            const int ntile = n2 >> 7;
            const int c     = k2 >> 6;
            const size_t base = (size_t)(((z * 4 + ntile) * 8 + c)) * BLKB;
            const uint32_t off = sw128((uint32_t)((n2 & 127) * 128 + (k2 & 63) * 2));
            *reinterpret_cast<__half*>(gW + base + off) =
                __float2half_rn(s[ty + i * 8][tx]);
        }
    } else {
        const float* __restrict__ X = z ? amino : atoms;
        const int cb = blockIdx.x - 256;
        const int m  = cb >> 3;
        const int c  = cb & 7;
        float4 v[8];
        int   rows[8], cols[8];
#pragma unroll
        for (int it = 0; it < 8; it++) {
            const int gidx = it * 1024 + tid * 4;
            rows[it] = gidx >> 6;
            cols[it] = gidx & 63;
            v[it] = *reinterpret_cast<const float4*>(
                &X[(size_t)(m * 128 + rows[it]) * DIM + c * 64 + cols[it]]);
        }
        char* dst = gA + (size_t)((z * 48 + m) * 8 + c) * BLKB;
#pragma unroll
        for (int it = 0; it < 8; it++) {
            __half2 h0 = __floats2half2_rn(v[it].x, v[it].y);
            __half2 h1 = __floats2half2_rn(v[it].z, v[it].w);
            uint2 o = make_uint2(*reinterpret_cast<uint32_t*>(&h0),
                                 *reinterpret_cast<uint32_t*>(&h1));
            const uint32_t off =
                sw128((uint32_t)(rows[it] * 128 + cols[it] * 2));
            *reinterpret_cast<uint2*>(dst + off) = o;
        }
    }
}

// --------------------------------------------------- persistent HMMA GEMM
// grid 296, 256 threads (8 warps, warp tile 64x32); barrier-free ring pipe
__global__ void __launch_bounds__(256, 2)
biatt_gemm_kernel(const float* __restrict__ bcc,
                  const float* __restrict__ bcp,
                  float* __restrict__ out) {
    extern __shared__ __align__(16) char sm[];
    const uint32_t sbase = smem_u32(sm);

    const int tid  = threadIdx.x;
    const int wid  = tid >> 5;
    const int lane = tid & 31;
    const int mw   = (wid >> 2) * 64;     // warp m offset (0 or 64)
    const int nw   = (wid & 3) * 32;      // warp n offset (0,32,64,96)
    const char* gA = reinterpret_cast<const char*>(g_A4);
    const char* gW = reinterpret_cast<const char*>(g_W4);

    // ldmatrix lane constants (swizzled rows of 128B, XOR (R&7)<<4).
    const uint32_t rowA  = (uint32_t)(mw + (lane & 15)) * 128;
    const uint32_t xA    = (uint32_t)(((lane & 15) & 7) << 4);
    const uint32_t colA0 = (uint32_t)((lane >> 4) << 4);
    const uint32_t rowB  = (uint32_t)(nw + ((lane >> 4) << 3) + (lane & 7)) * 128;
    const uint32_t xB    = (uint32_t)((lane & 7) << 4);
    const uint32_t colB0 = (uint32_t)(((lane >> 3) & 1) << 4);

    const uint32_t fullB  = sbase + SM_MBAR;        // full[s]  at +8s
    const uint32_t emptyB = sbase + SM_MBAR + 24;   // empty[s] at +8s

    if (tid == 0) {
#pragma unroll
        for (int s = 0; s < 3; ++s) {
            mbar_init(fullB  + s * 8, 1);
            mbar_init(emptyB + s * 8, NWARP);
        }
    }
    __syncthreads();   // only CTA-wide barrier in the kernel

    const int ntiles  = (blockIdx.x + NPERS < NTILES) ? 2 : 1;
    const int nchunks = ntiles * NCHUNK;

    // ---- producer prologue: chunks 0,1 of tile 0 into stages 0,1
    if (tid == 0) {
        const int t0  = blockIdx.x;
        const int z   = t0 / 192;
        const int rem = t0 - z * 192;
        const char* sA = gA + (size_t)((z * 48 + (rem >> 2)) * 8) * BLKB;
        const char* sB = gW + (size_t)((z * 4  + (rem & 3))  * 8) * BLKB;
#pragma unroll
        for (int p = 0; p < 2; ++p) {
            const uint32_t st = sbase + (uint32_t)(p * SM_STAGE);
            mbar_expect(fullB + p * 8, 2 * BLKB);
            bulk_cp(st + SM_A, sA + (size_t)p * BLKB, BLKB, fullB + p * 8);
            bulk_cp(st + SM_B, sB + (size_t)p * BLKB, BLKB, fullB + p * 8);
        }
    }

    float acc[4][4][4];
#pragma unroll
    for (int i = 0; i < 4; i++)
#pragma unroll
        for (int j = 0; j < 4; j++)
#pragma unroll
            for (int e = 0; e < 4; e++) acc[i][j][e] = 0.f;

    uint32_t fpm = 0;   // consumer parity per stage
    uint32_t epm = 0;   // producer (empty) parity per stage

    for (int g = 0; g < nchunks; ++g) {
        const int s = g % 3;

        // ---- producer: refill stage (g+2)%3 with chunk g+2
        if (tid == 0 && g + 2 < nchunks) {
            const int gg = g + 2;
            const int s2 = gg % 3;
            if (gg >= 3) {   // stage reused: wait all 8 warps drained prior use
                mbar_wait(emptyB + s2 * 8, (epm >> s2) & 1u);
                epm ^= 1u << s2;
            }
            const int t   = blockIdx.x + (gg >> 3) * NPERS;
            const int z   = t / 192;
            const int rem = t - z * 192;
            const int c   = gg & 7;
            const char* sA = gA + (size_t)((z * 48 + (rem >> 2)) * 8 + c) * BLKB;
            const char* sB = gW + (size_t)((z * 4  + (rem & 3))  * 8 + c) * BLKB;
            const uint32_t st = sbase + (uint32_t)(s2 * SM_STAGE);
            mbar_expect(fullB + s2 * 8, 2 * BLKB);
            bulk_cp(st + SM_A, sA, BLKB, fullB + s2 * 8);
            bulk_cp(st + SM_B, sB, BLKB, fullB + s2 * 8);
        }

        // ---- consumer: wait data, compute
        mbar_wait(fullB + s * 8, (fpm >> s) & 1u);
        fpm ^= 1u << s;

        const uint32_t stb = sbase + (uint32_t)(s * SM_STAGE);
        const uint32_t aBase = stb + SM_A + rowA;
        const uint32_t bBase = stb + SM_B + rowB;
#pragma unroll
        for (int ks = 0; ks < 4; ++ks) {
            const uint32_t cb = (uint32_t)(ks * 32);
            const uint32_t aCol = (colA0 + cb) ^ xA;
            const uint32_t bCol = (colB0 + cb) ^ xB;
            uint32_t af[4][4];
#pragma unroll
            for (int mt = 0; mt < 4; ++mt)
                ldsm_x4(af[mt], aBase + mt * 2048 + aCol);
#pragma unroll
            for (int j2 = 0; j2 < 2; ++j2) {
                uint32_t bf[4];
                ldsm_x4(bf, bBase + j2 * 2048 + bCol);
#pragma unroll
                for (int mt = 0; mt < 4; ++mt) {
                    mma_f16(acc[mt][j2 * 2],     af[mt], bf[0], bf[1]);
                    mma_f16(acc[mt][j2 * 2 + 1], af[mt], bf[2], bf[3]);
                }
            }
        }
        if (lane == 0) mbar_arrive(emptyB + s * 8);   // stage drained (this warp)

        // ---- per-warp epilogue at tile end (overlaps other warps' compute)
        if ((g & 7) == 7) {
            const int t   = blockIdx.x + (g >> 3) * NPERS;
            const int z   = t / 192;
            const int rem = t - z * 192;
            const int n0  = (rem & 3) * BN;
            const int m0  = (rem >> 2) * BM;
            const float* __restrict__ bias = (z ? bcp : bcc) + n0;
            float* C = out + (size_t)z * M_ROWS * DIM + (size_t)m0 * DIM + n0;
#pragma unroll
            for (int mt = 0; mt < 4; ++mt) {
                const int r0 = mw + mt * 16 + (lane >> 2);
#pragma unroll
                for (int nt = 0; nt < 4; ++nt) {
                    const int cl = nw + nt * 8 + (lane & 3) * 2;
                    const float2 bv = __ldg(reinterpret_cast<const float2*>(bias + cl));
                    float2 v0 = make_float2(acc[mt][nt][0] + bv.x,
                                            acc[mt][nt][1] + bv.y);
                    float2 v1 = make_float2(acc[mt][nt][2] + bv.x,
                                            acc[mt][nt][3] + bv.y);
                    *reinterpret_cast<float2*>(&C[(size_t)r0 * DIM + cl]) = v0;
                    *reinterpret_cast<float2*>(&C[(size_t)(r0 + 8) * DIM + cl]) = v1;
                    acc[mt][nt][0] = 0.f; acc[mt][nt][1] = 0.f;
                    acc[mt][nt][2] = 0.f; acc[mt][nt][3] = 0.f;
                }
            }
        }
    }
}

// ------------------------------------------------------------------ launch
extern "C" void kernel_launch(void* const* d_in, const int* in_sizes, int n_in,
                              void* d_out, int out_size) {
    const float* atoms = (const float*)d_in[0];
    const float* amino = (const float*)d_in[1];
    const float* Wcc   = (const float*)d_in[15];
    const float* bcc   = (const float*)d_in[16];
    const float* Wcp   = (const float*)d_in[17];
    const float* bcp   = (const float*)d_in[18];
    float* out = (float*)d_out;

    static bool attr_set = false;
    if (!attr_set) {
        cudaFuncSetAttribute(biatt_gemm_kernel,
                             cudaFuncAttributeMaxDynamicSharedMemorySize, SM_TOT);
        attr_set = true;
    }

    prep_kernel<<<dim3(256 + 384, 2), 256>>>(atoms, amino, Wcc, Wcp);
    biatt_gemm_kernel<<<NPERS, 256, SM_TOT>>>(bcc, bcp, out);
}